// round 1
// baseline (speedup 1.0000x reference)
#include <cuda_runtime.h>
#include <cstddef>

// Fixed problem sizes (reference: N_NODES=100000, IN_F=HID_F=64, OUT_F=32)
#define NODES_MAX 100000

// Scratch (allocation-free rule: __device__ globals)
__device__ float g_f1[NODES_MAX * 64];    // features @ W1
__device__ float g_agg1[NODES_MAX * 64];  // segment_sum(f1[src] -> dst)
__device__ float g_f2[NODES_MAX * 32];    // relu(agg1 + b1) @ W2

// ---------------------------------------------------------------------------
// Zero a float buffer via float4 stores
// ---------------------------------------------------------------------------
__global__ void zero_kernel(float4* __restrict__ p, int n4) {
    int i = blockIdx.x * blockDim.x + threadIdx.x;
    if (i < n4) p[i] = make_float4(0.f, 0.f, 0.f, 0.f);
}

// ---------------------------------------------------------------------------
// Initialize output rows with bias b2 (row stride 32)
// ---------------------------------------------------------------------------
__global__ void init_out_kernel(float* __restrict__ out,
                                const float* __restrict__ b2, int total) {
    int i = blockIdx.x * blockDim.x + threadIdx.x;
    if (i < total) out[i] = __ldg(b2 + (i & 31));
}

// ---------------------------------------------------------------------------
// Row transform: Y[row] = act(X[row]) @ W  with  act = relu(x + b_in) if
// RELU_BIAS else identity. IN fixed at 64, OUTF templated (64 or 32).
// One thread per row; W (64*OUTF floats) staged in smem, read as broadcast.
// ---------------------------------------------------------------------------
template <int OUTF, bool RELU_BIAS>
__global__ void transform_kernel(const float* __restrict__ X,
                                 const float* __restrict__ W,
                                 const float* __restrict__ b_in,
                                 float* __restrict__ Y, int n) {
    __shared__ float Ws[64 * OUTF];
    __shared__ float bs[64];
    for (int i = threadIdx.x; i < 64 * OUTF; i += blockDim.x) Ws[i] = W[i];
    if (RELU_BIAS) {
        for (int i = threadIdx.x; i < 64; i += blockDim.x) bs[i] = b_in[i];
    }
    __syncthreads();

    int row = blockIdx.x * blockDim.x + threadIdx.x;
    if (row >= n) return;

    float x[64];
    const float4* xr = reinterpret_cast<const float4*>(X + (size_t)row * 64);
#pragma unroll
    for (int i = 0; i < 16; i++) {
        float4 v = xr[i];
        x[4 * i + 0] = v.x; x[4 * i + 1] = v.y;
        x[4 * i + 2] = v.z; x[4 * i + 3] = v.w;
    }
    if (RELU_BIAS) {
#pragma unroll
        for (int k = 0; k < 64; k++) x[k] = fmaxf(x[k] + bs[k], 0.f);
    }

    float acc[OUTF];
#pragma unroll
    for (int j = 0; j < OUTF; j++) acc[j] = 0.f;

#pragma unroll 8
    for (int k = 0; k < 64; k++) {
        float xv = x[k];
#pragma unroll
        for (int j = 0; j < OUTF; j++)
            acc[j] = fmaf(xv, Ws[k * OUTF + j], acc[j]);
    }

    float4* yr = reinterpret_cast<float4*>(Y + (size_t)row * OUTF);
#pragma unroll
    for (int i = 0; i < OUTF / 4; i++)
        yr[i] = make_float4(acc[4 * i], acc[4 * i + 1],
                            acc[4 * i + 2], acc[4 * i + 3]);
}

// ---------------------------------------------------------------------------
// Edge scatter-add: out[dst[e]] += F[src[e]] (feature width = 4 << LOGC),
// vectorized with red.global.add.v4.f32 (one 16B vector RED per thread).
// Thread layout: idx -> (e = idx>>LOGC, chunk c = idx & (C-1)); consecutive
// threads cover consecutive 16B chunks of the same edge row (coalesced gather).
// ---------------------------------------------------------------------------
template <int LOGC>
__global__ void scatter_red_kernel(const float* __restrict__ F,
                                   const int* __restrict__ src,
                                   const int* __restrict__ dst,
                                   float* __restrict__ out, int n_edges) {
    const int C = 1 << LOGC;        // float4 chunks per row
    const int FW = 4 << LOGC;       // floats per row
    int idx = blockIdx.x * blockDim.x + threadIdx.x;
    int total = n_edges << LOGC;
    if (idx >= total) return;
    int e = idx >> LOGC;
    int c = idx & (C - 1);
    int s = __ldg(src + e);
    int d = __ldg(dst + e);
    float4 v = *reinterpret_cast<const float4*>(F + (size_t)s * FW + c * 4);
    float* p = out + (size_t)d * FW + c * 4;
    asm volatile("red.global.add.v4.f32 [%0], {%1, %2, %3, %4};"
                 :: "l"(p), "f"(v.x), "f"(v.y), "f"(v.z), "f"(v.w)
                 : "memory");
}

// ---------------------------------------------------------------------------
// kernel_launch
// inputs: features[f32 N*64], src[i32 E], dst[i32 E], W1[f32 64*64],
//         b1[f32 64], W2[f32 64*32], b2[f32 32]; out: f32 N*32
// ---------------------------------------------------------------------------
extern "C" void kernel_launch(void* const* d_in, const int* in_sizes, int n_in,
                              void* d_out, int out_size) {
    const float* features = (const float*)d_in[0];
    const int*   src      = (const int*)d_in[1];
    const int*   dst      = (const int*)d_in[2];
    const float* W1       = (const float*)d_in[3];
    const float* b1       = (const float*)d_in[4];
    const float* W2       = (const float*)d_in[5];
    const float* b2       = (const float*)d_in[6];
    float*       out      = (float*)d_out;

    int n_nodes = in_sizes[0] / 64;
    int n_edges = in_sizes[1];

    void *pf1, *pagg1, *pf2;
    cudaGetSymbolAddress(&pf1, g_f1);
    cudaGetSymbolAddress(&pagg1, g_agg1);
    cudaGetSymbolAddress(&pf2, g_f2);
    float* f1   = (float*)pf1;
    float* agg1 = (float*)pagg1;
    float* f2   = (float*)pf2;

    const int TB = 128;
    int row_blocks = (n_nodes + TB - 1) / TB;

    // 1) f1 = features @ W1
    transform_kernel<64, false><<<row_blocks, TB>>>(features, W1, nullptr, f1, n_nodes);

    // 2) agg1 = 0
    {
        int n4 = n_nodes * 16;
        zero_kernel<<<(n4 + 255) / 256, 256>>>((float4*)agg1, n4);
    }

    // 3) agg1[dst] += f1[src]   (64 floats/edge, 16 v4-REDs)
    {
        int total = n_edges << 4;
        scatter_red_kernel<4><<<(total + 255) / 256, 256>>>(f1, src, dst, agg1, n_edges);
    }

    // 4) f2 = relu(agg1 + b1) @ W2
    transform_kernel<32, true><<<row_blocks, TB>>>(agg1, W2, b1, f2, n_nodes);

    // 5) out = b2 (broadcast per row)
    {
        int total = n_nodes * 32;
        init_out_kernel<<<(total + 255) / 256, 256>>>(out, b2, total);
    }

    // 6) out[dst] += f2[src]    (32 floats/edge, 8 v4-REDs)
    {
        int total = n_edges << 3;
        scatter_red_kernel<3><<<(total + 255) / 256, 256>>>(f2, src, dst, out, n_edges);
    }
}